// round 9
// baseline (speedup 1.0000x reference)
#include <cuda_runtime.h>
#include <math.h>

// ---------------------------------------------------------------------------
// RadiomicsPreservationLoss — cp.async pipelined stencil.
// Each warp owns a private 4-stage smem ring (2 images x 136-col rows + mask).
// Loads go global->smem via cp.async (no RF cost, deep prefetch); consume via
// LDS (lat 29). No shuffles, no barriers in the mainloop, halo = smem columns.
// Balanced 18/19-row runs per warp. Fused last-block finalize.
// ---------------------------------------------------------------------------

#define HH 512
#define WW 512
#define BB 32
#define NBLK 444                 // 3 blocks/SM
#define NTHR 256
#define NSLOTS (NBLK * 8)        // 3552 warp slots
#define RU 65536                 // 128 stripcols * 512 rows
#define RUQ 18                   // RU / NSLOTS
#define RUR 1600                 // RU % NSLOTS
#define DPTH 4
#define ROWF 136                 // 4 halo + 128 + 4 halo (floats)
#define WSM (2 * DPTH * ROWF + DPTH * 128)   // floats per warp = 1600
#define SMEM_BYTES (WSM * 8 * 4)             // 51200 B per block
#define FULLM 0xffffffffu

__device__ double g_part[NBLK][11];
__device__ unsigned g_cnt = 0;

__device__ __forceinline__ unsigned s2u(const void* p) {
    return (unsigned)__cvta_generic_to_shared(p);
}
// Guarded cp.async, 16B, with src_size (0 => full zero-fill of dst).
__device__ __forceinline__ void cpa16g(unsigned dst, const float* src, int sz, int guard) {
    asm volatile(
        "{ .reg .pred p; setp.ne.b32 p, %3, 0;\n"
        " @p cp.async.ca.shared.global [%0], [%1], 16, %2;\n}"
        :: "r"(dst), "l"(src), "r"(sz), "r"(guard) : "memory");
}
#define CPA_COMMIT()  asm volatile("cp.async.commit_group;" ::: "memory")
#define CPA_WAIT1()   asm volatile("cp.async.wait_group 1;" ::: "memory")
#define CPA_WAIT0()   asm volatile("cp.async.wait_group 0;" ::: "memory")

// Issue pipeline stage s for a segment: image row (ra-1+s) of both images into
// ring slot s&3, mask row (ra+s) if s<n. Zero-fill outside image / halo edges.
__device__ __forceinline__ void issue_stage(
    int s, int ra, int n,
    const float* __restrict__ bi, const float* __restrict__ bo,
    const float* __restrict__ bm,
    int c0, int hasL, int hasR, int lane,
    unsigned smi0, unsigned smi1, unsigned smm)
{
    const int slotd = s & 3;
    const int rr = ra - 1 + s;
    const int rv = ((unsigned)rr < (unsigned)HH) ? 1 : 0;
    const int rro = rv ? rr : 0;
    const float* pi = bi + rro * WW + c0;
    const float* po = bo + rro * WW + c0;
    const int mainsz = rv ? 16 : 0;
    const unsigned rowoff = (unsigned)slotd * (ROWF * 4);

    // main 128 cols: lane's 16B chunk at smem col 4*lane+4
    cpa16g(smi0 + rowoff + 16 + lane * 16, pi + lane * 4, mainsz, 1);
    cpa16g(smi1 + rowoff + 16 + lane * 16, po + lane * 4, mainsz, 1);

    // halo chunks: lane 0 -> left (smem col 0 = gmem c0-4..c0-1),
    //              lane 1 -> right (smem col 132 = gmem c0+128..c0+131)
    const int g = (lane < 2) ? 1 : 0;
    const int h = (lane == 0) ? hasL : hasR;
    const int hvalid = rv & h;
    const int hoff = (lane == 0) ? -4 : 128;
    const int hsz = hvalid ? 16 : 0;
    const unsigned hcol = (lane == 0) ? 0u : (132u * 4u);
    const float* hpi = pi + (hvalid ? hoff : 0);
    const float* hpo = po + (hvalid ? hoff : 0);
    cpa16g(smi0 + rowoff + hcol, hpi, hsz, g);
    cpa16g(smi1 + rowoff + hcol, hpo, hsz, g);

    // mask row ra+s (only while s < n)
    const int mg = (s < n) ? 1 : 0;
    const float* pm = bm + (mg ? (ra + s) : 0) * WW + c0;
    cpa16g(smm + (unsigned)slotd * 512 + lane * 16, pm + lane * 4, 16, mg);
}

// Read 6 contiguous columns (cb-1 .. cb+4) of one smem row.
__device__ __forceinline__ void rd6(const float* __restrict__ wrow, int lane,
                                    float* __restrict__ b)
{
    const float* p = wrow + 4 * lane;
    b[0] = p[3];
    float4 q = *(const float4*)(p + 4);
    b[1] = q.x; b[2] = q.y; b[3] = q.z; b[4] = q.w;
    b[5] = p[8];
}

// 3x3 variance, laplacian, center for 4 pixels from three 6-wide rows
// (contiguous col indexing: pixel p is column b[p+1]).
__device__ __forceinline__ void proc6c(
    const float* __restrict__ A0, const float* __restrict__ A1,
    const float* __restrict__ A2,
    float* __restrict__ var, float* __restrict__ lap, float* __restrict__ cen)
{
    float cs[6], cq[6];
    #pragma unroll
    for (int j = 0; j < 6; j++) {
        cs[j] = A0[j] + A1[j] + A2[j];
        float u = A0[j] * A0[j];
        u = fmaf(A1[j], A1[j], u);
        cq[j] = fmaf(A2[j], A2[j], u);
    }
    const float inv9 = 1.f / 9.f;
    #pragma unroll
    for (int p = 0; p < 4; p++) {
        float S = cs[p] + cs[p + 1] + cs[p + 2];
        float Q = cq[p] + cq[p + 1] + cq[p + 2];
        float bmn = S * inv9;
        var[p] = fmaf(-bmn, bmn, Q * inv9);
        lap[p] = fmaf(-5.f, A1[p + 1], cs[p + 1] + A1[p] + A1[p + 2]);
        cen[p] = A1[p + 1];
    }
}

__global__ void __launch_bounds__(NTHR, 3) k_main(
    const float* __restrict__ g_in,
    const float* __restrict__ g_out,
    const float* __restrict__ g_mask,
    float* __restrict__ final_out)
{
    extern __shared__ float dsm[];
    __shared__ float sred[11][8];
    __shared__ bool s_last;
    __shared__ double sacc[11];

    const int t    = threadIdx.x;
    const int lane = t & 31;
    const int wid  = t >> 5;
    const int slot = blockIdx.x * 8 + wid;   // 0..3551

    float* wbase = dsm + wid * WSM;
    const float* w0 = wbase;                    // img0 ring [DPTH][ROWF]
    const float* w1 = wbase + DPTH * ROWF;      // img1 ring
    const float* wm = wbase + 2 * DPTH * ROWF;  // mask ring [DPTH][128]
    const unsigned smi0 = s2u(wbase);
    const unsigned smi1 = smi0 + DPTH * ROWF * 4;
    const unsigned smm  = smi0 + 2 * DPTH * ROWF * 4;

    float msum = 0.f;
    float xi1 = 0.f, xi2 = 0.f, xi3 = 0.f, xi4 = 0.f;
    float yo1 = 0.f, yo2 = 0.f, yo3 = 0.f, yo4 = 0.f;
    float texs = 0.f, shps = 0.f;

    // balanced contiguous run of row-units
    int u    = slot * RUQ + min(slot, RUR);
    const int uend = u + RUQ + (slot < RUR ? 1 : 0);

    while (u < uend) {
        const int scol = u >> 9;               // stripcol 0..127
        const int ra   = u & 511;              // first output row in this col
        const int n    = min(uend - u, HH - ra);
        const int img  = scol >> 2;
        const int strip = scol & 3;
        const int c0   = strip << 7;
        const int hasL = (strip > 0) ? 1 : 0;
        const int hasR = (strip < 3) ? 1 : 0;

        const size_t ib = (size_t)img * (HH * WW);
        const float* bi = g_in   + ib;
        const float* bo = g_out  + ib;
        const float* bm = g_mask + ib;

        // drain previous segment's in-flight copies before reusing slots
        CPA_WAIT0();
        __syncwarp();

        issue_stage(0, ra, n, bi, bo, bm, c0, hasL, hasR, lane, smi0, smi1, smm);
        CPA_COMMIT();
        issue_stage(1, ra, n, bi, bo, bm, c0, hasL, hasR, lane, smi0, smi1, smm);
        CPA_COMMIT();
        issue_stage(2, ra, n, bi, bo, bm, c0, hasL, hasR, lane, smi0, smi1, smm);
        CPA_COMMIT();

        for (int k = 0; k < n; k++) {
            issue_stage(k + 3, ra, n, bi, bo, bm, c0, hasL, hasR, lane, smi0, smi1, smm);
            CPA_COMMIT();
            CPA_WAIT1();            // stages <= k+2 complete
            __syncwarp();           // cross-lane visibility

            const int s0 = k & 3, s1 = (k + 1) & 3, s2 = (k + 2) & 3;

            float A0[6], A1[6], A2[6];
            float vi[4], li[4], xc[4];
            rd6(w0 + s0 * ROWF, lane, A0);
            rd6(w0 + s1 * ROWF, lane, A1);
            rd6(w0 + s2 * ROWF, lane, A2);
            proc6c(A0, A1, A2, vi, li, xc);

            float vo[4], lo[4], yc[4];
            rd6(w1 + s0 * ROWF, lane, A0);
            rd6(w1 + s1 * ROWF, lane, A1);
            rd6(w1 + s2 * ROWF, lane, A2);
            proc6c(A0, A1, A2, vo, lo, yc);

            float4 m0 = *(const float4*)(wm + s0 * 128 + 4 * lane);
            float mv[4] = { m0.x, m0.y, m0.z, m0.w };

            #pragma unroll
            for (int j = 0; j < 4; j++) {
                float m = mv[j];
                msum += m;
                float x = xc[j], y = yc[j];
                float x2 = x * x, y2 = y * y;
                float qx = x2 * m, qy = y2 * m;
                xi1 = fmaf(x, m, xi1);  xi2 += qx;
                xi3 = fmaf(x, qx, xi3); xi4 = fmaf(x2, qx, xi4);
                yo1 = fmaf(y, m, yo1);  yo2 += qy;
                yo3 = fmaf(y, qy, yo3); yo4 = fmaf(y2, qy, yo4);
                texs = fmaf(fabsf(vo[j] - vi[j]), m, texs);
                shps = fmaf(fabsf(lo[j] - li[j]), m, shps);
            }
        }
        u += n;
    }

    // ---- block reduction -> fp64 partial ----
    float acc[11] = { msum, xi1, xi2, xi3, xi4, yo1, yo2, yo3, yo4, texs, shps };
    #pragma unroll
    for (int k = 0; k < 11; k++) {
        float v = acc[k];
        #pragma unroll
        for (int off = 16; off; off >>= 1)
            v += __shfl_xor_sync(FULLM, v, off);
        if (lane == 0) sred[k][wid] = v;
    }
    __syncthreads();
    if (t < 11) {
        double s = 0.0;
        #pragma unroll
        for (int w = 0; w < 8; w++) s += (double)sred[t][w];
        g_part[blockIdx.x][t] = s;
    }

    // ---- last-block finalize ----
    __threadfence();
    if (t == 0) {
        unsigned prev = atomicAdd(&g_cnt, 1u);
        s_last = (prev == NBLK - 1);
    }
    __syncthreads();
    if (!s_last) return;

    for (int k = wid; k < 11; k += 8) {
        double s = 0.0;
        for (int b = lane; b < NBLK; b += 32)
            s += g_part[b][k];
        #pragma unroll
        for (int off = 16; off; off >>= 1)
            s += __shfl_xor_sync(FULLM, s, off);
        if (lane == 0) sacc[k] = s;
    }
    __syncthreads();

    if (t == 0) {
        g_cnt = 0;   // reset for next graph replay
        const double EPS = 1e-8;
        const double NTOT = (double)BB * HH * WW;

        double M0 = sacc[0];
        double ms = M0 + EPS;
        double Mi1 = sacc[1], Mi2 = sacc[2], Mi3 = sacc[3], Mi4 = sacc[4];
        double Mo1 = sacc[5], Mo2 = sacc[6], Mo3 = sacc[7], Mo4 = sacc[8];

        double im = Mi1 / ms, om = Mo1 / ms;
        double im2 = im * im, om2 = om * om;

        double c2i = Mi2 - 2.0 * im * Mi1 + im2 * M0;
        double c3i = Mi3 - 3.0 * im * Mi2 + 3.0 * im2 * Mi1 - im2 * im * M0;
        double c4i = Mi4 - 4.0 * im * Mi3 + 6.0 * im2 * Mi2 - 4.0 * im2 * im * Mi1 + im2 * im2 * M0;

        double c2o = Mo2 - 2.0 * om * Mo1 + om2 * M0;
        double c3o = Mo3 - 3.0 * om * Mo2 + 3.0 * om2 * Mo1 - om2 * om * M0;
        double c4o = Mo4 - 4.0 * om * Mo3 + 6.0 * om2 * Mo2 - 4.0 * om2 * om * Mo1 + om2 * om2 * M0;

        double iv = c2i / ms, ov = c2o / ms;
        double isk = c3i / (ms * (iv * sqrt(iv) + EPS));
        double osk = c3o / (ms * (ov * sqrt(ov) + EPS));
        double iku = c4i / (ms * (iv * iv + EPS));
        double oku = c4o / (ms * (ov * ov + EPS));

        double dm = im - om, dv = iv - ov, dsk = isk - osk, dku = iku - oku;
        double inten = dm * dm + dv * dv + dsk * dsk + dku * dku;
        double tex = sacc[9]  / NTOT;
        double shp = sacc[10] / NTOT;
        double total = inten + tex + 0.5 * shp;

        final_out[0] = (float)inten;
        final_out[1] = (float)tex;
        final_out[2] = (float)shp;
        final_out[3] = (float)total;
    }
}

extern "C" void kernel_launch(void* const* d_in, const int* in_sizes, int n_in,
                              void* d_out, int out_size) {
    const float* in_img  = (const float*)d_in[0];
    const float* out_img = (const float*)d_in[1];
    const float* mask    = (const float*)d_in[2];

    cudaFuncSetAttribute(k_main, cudaFuncAttributeMaxDynamicSharedMemorySize,
                         SMEM_BYTES);
    k_main<<<NBLK, NTHR, SMEM_BYTES>>>(in_img, out_img, mask, (float*)d_out);
}

// round 10
// speedup vs baseline: 1.0890x; 1.0890x over previous
#include <cuda_runtime.h>
#include <math.h>

// ---------------------------------------------------------------------------
// RadiomicsPreservationLoss — shuffle-free stencil with redundant neighbor
// loads: each lane LDGs its own float4 + left/right neighbor scalars (L1 hits
// from adjacent lanes' lines). No SHFL, no SEL halo machinery, column guards
// are per-segment constants. Balanced contiguous row-runs, occ-3, 444 blocks,
// fused last-block finalize.
// inputs: input_img, output_img, roi_mask  [32,1,512,512] f32
// output: [intensity, texture, shape, total] (4 x f32)
// ---------------------------------------------------------------------------

#define HH 512
#define WW 512
#define BB 32
#define NBLK 444                 // 3 blocks/SM
#define NTHR 256
#define NSLOTS (NBLK * 8)        // 3552 warp slots
#define RU 65536                 // 128 stripcols * 512 rows
#define RUQ (RU / NSLOTS)        // 18
#define RUR (RU % NSLOTS)        // 1600
#define FULLM 0xffffffffu

__device__ double g_part[NBLK][11];
__device__ unsigned g_cnt = 0;

// 3x3 variance + laplacian + center for the lane's 4 pixels.
// p points at (r, cb). 9 loads, all independent; cl/cr are segment constants.
__device__ __forceinline__ void sten(
    const float* __restrict__ p, bool okm, bool okp, bool cl, bool cr,
    float* __restrict__ var, float* __restrict__ lap, float* __restrict__ cen)
{
    const float4 z4 = make_float4(0.f, 0.f, 0.f, 0.f);
    float4 qm = okm ? *(const float4*)(p - WW) : z4;
    float4 qc = *(const float4*)p;
    float4 qp = okp ? *(const float4*)(p + WW) : z4;
    float lT = (cl & okm) ? p[-WW - 1] : 0.f;
    float lC =  cl        ? p[-1]      : 0.f;
    float lB = (cl & okp) ? p[ WW - 1] : 0.f;
    float rT = (cr & okm) ? p[-WW + 4] : 0.f;
    float rC =  cr        ? p[4]       : 0.f;
    float rB = (cr & okp) ? p[ WW + 4] : 0.f;

    float A0[6] = { lT, qm.x, qm.y, qm.z, qm.w, rT };
    float A1[6] = { lC, qc.x, qc.y, qc.z, qc.w, rC };
    float A2[6] = { lB, qp.x, qp.y, qp.z, qp.w, rB };

    float cs[6], cq[6];
    #pragma unroll
    for (int j = 0; j < 6; j++) {
        cs[j] = A0[j] + A1[j] + A2[j];
        float u = A0[j] * A0[j];
        u = fmaf(A1[j], A1[j], u);
        cq[j] = fmaf(A2[j], A2[j], u);
    }
    const float inv9 = 1.f / 9.f;
    #pragma unroll
    for (int j = 0; j < 4; j++) {
        float S = cs[j] + cs[j + 1] + cs[j + 2];
        float Q = cq[j] + cq[j + 1] + cq[j + 2];
        float bmn = S * inv9;
        var[j] = fmaf(-bmn, bmn, Q * inv9);
        lap[j] = fmaf(-5.f, A1[j + 1], cs[j + 1] + A1[j] + A1[j + 2]);
        cen[j] = A1[j + 1];
    }
}

__global__ void __launch_bounds__(NTHR, 3) k_main(
    const float* __restrict__ g_in,
    const float* __restrict__ g_out,
    const float* __restrict__ g_mask,
    float* __restrict__ final_out)
{
    __shared__ float sred[11][8];
    __shared__ bool s_last;
    __shared__ double sacc[11];

    const int t    = threadIdx.x;
    const int lane = t & 31;
    const int wid  = t >> 5;
    const int slot = blockIdx.x * 8 + wid;   // 0..3551

    float msum = 0.f;
    float xi1 = 0.f, xi2 = 0.f, xi3 = 0.f, xi4 = 0.f;
    float yo1 = 0.f, yo2 = 0.f, yo3 = 0.f, yo4 = 0.f;
    float texs = 0.f, shps = 0.f;

    // balanced contiguous run of row-units (stripcol-major, row minor)
    int u = slot * RUQ + min(slot, RUR);
    const int uend = u + RUQ + (slot < RUR ? 1 : 0);

    while (u < uend) {
        const int scol  = u >> 9;              // stripcol 0..127
        const int ra    = u & 511;             // first row in this run
        const int n     = min(uend - u, HH - ra);
        const int img   = scol >> 2;
        const int strip = scol & 3;
        const int cb    = (strip << 7) + lane * 4;
        const bool cl   = (cb > 0);            // left col exists in image
        const bool cr   = (cb < WW - 4);       // right col exists in image

        const size_t base = (size_t)img * (HH * WW) + (size_t)ra * WW + cb;
        const float* pi = g_in   + base;
        const float* po = g_out  + base;
        const float* pm = g_mask + base;

        for (int k = 0; k < n; k++) {
            const int r = ra + k;
            const bool okm = (r > 0);
            const bool okp = (r < HH - 1);

            float4 m0 = *(const float4*)pm;    // mask joins the load batch

            float vi[4], li[4], xc[4];
            sten(pi, okm, okp, cl, cr, vi, li, xc);
            float vo[4], lo[4], yc[4];
            sten(po, okm, okp, cl, cr, vo, lo, yc);

            float mv[4] = { m0.x, m0.y, m0.z, m0.w };
            #pragma unroll
            for (int j = 0; j < 4; j++) {
                float m = mv[j];
                msum += m;
                float x = xc[j], y = yc[j];
                float x2 = x * x, y2 = y * y;
                float qx = x2 * m, qy = y2 * m;
                xi1 = fmaf(x, m, xi1);  xi2 += qx;
                xi3 = fmaf(x, qx, xi3); xi4 = fmaf(x2, qx, xi4);
                yo1 = fmaf(y, m, yo1);  yo2 += qy;
                yo3 = fmaf(y, qy, yo3); yo4 = fmaf(y2, qy, yo4);
                texs = fmaf(fabsf(vo[j] - vi[j]), m, texs);
                shps = fmaf(fabsf(lo[j] - li[j]), m, shps);
            }

            pi += WW; po += WW; pm += WW;
        }
        u += n;
    }

    // ---- block reduction -> fp64 partial ----
    float acc[11] = { msum, xi1, xi2, xi3, xi4, yo1, yo2, yo3, yo4, texs, shps };
    #pragma unroll
    for (int k = 0; k < 11; k++) {
        float v = acc[k];
        #pragma unroll
        for (int off = 16; off; off >>= 1)
            v += __shfl_xor_sync(FULLM, v, off);
        if (lane == 0) sred[k][wid] = v;
    }
    __syncthreads();
    if (t < 11) {
        double s = 0.0;
        #pragma unroll
        for (int w = 0; w < 8; w++) s += (double)sred[t][w];
        g_part[blockIdx.x][t] = s;
    }

    // ---- last-block finalize ----
    __threadfence();
    if (t == 0) {
        unsigned prev = atomicAdd(&g_cnt, 1u);
        s_last = (prev == NBLK - 1);
    }
    __syncthreads();
    if (!s_last) return;

    for (int k = wid; k < 11; k += 8) {
        double s = 0.0;
        for (int b = lane; b < NBLK; b += 32)
            s += g_part[b][k];
        #pragma unroll
        for (int off = 16; off; off >>= 1)
            s += __shfl_xor_sync(FULLM, s, off);
        if (lane == 0) sacc[k] = s;
    }
    __syncthreads();

    if (t == 0) {
        g_cnt = 0;   // reset for next graph replay
        const double EPS = 1e-8;
        const double NTOT = (double)BB * HH * WW;

        double M0 = sacc[0];
        double ms = M0 + EPS;
        double Mi1 = sacc[1], Mi2 = sacc[2], Mi3 = sacc[3], Mi4 = sacc[4];
        double Mo1 = sacc[5], Mo2 = sacc[6], Mo3 = sacc[7], Mo4 = sacc[8];

        double im = Mi1 / ms, om = Mo1 / ms;
        double im2 = im * im, om2 = om * om;

        double c2i = Mi2 - 2.0 * im * Mi1 + im2 * M0;
        double c3i = Mi3 - 3.0 * im * Mi2 + 3.0 * im2 * Mi1 - im2 * im * M0;
        double c4i = Mi4 - 4.0 * im * Mi3 + 6.0 * im2 * Mi2 - 4.0 * im2 * im * Mi1 + im2 * im2 * M0;

        double c2o = Mo2 - 2.0 * om * Mo1 + om2 * M0;
        double c3o = Mo3 - 3.0 * om * Mo2 + 3.0 * om2 * Mo1 - om2 * om * M0;
        double c4o = Mo4 - 4.0 * om * Mo3 + 6.0 * om2 * Mo2 - 4.0 * om2 * om * Mo1 + om2 * om2 * M0;

        double iv = c2i / ms, ov = c2o / ms;
        double isk = c3i / (ms * (iv * sqrt(iv) + EPS));
        double osk = c3o / (ms * (ov * sqrt(ov) + EPS));
        double iku = c4i / (ms * (iv * iv + EPS));
        double oku = c4o / (ms * (ov * ov + EPS));

        double dm = im - om, dv = iv - ov, dsk = isk - osk, dku = iku - oku;
        double inten = dm * dm + dv * dv + dsk * dsk + dku * dku;
        double tex = sacc[9]  / NTOT;
        double shp = sacc[10] / NTOT;
        double total = inten + tex + 0.5 * shp;

        final_out[0] = (float)inten;
        final_out[1] = (float)tex;
        final_out[2] = (float)shp;
        final_out[3] = (float)total;
    }
}

extern "C" void kernel_launch(void* const* d_in, const int* in_sizes, int n_in,
                              void* d_out, int out_size) {
    const float* in_img  = (const float*)d_in[0];
    const float* out_img = (const float*)d_in[1];
    const float* mask    = (const float*)d_in[2];

    k_main<<<NBLK, NTHR>>>(in_img, out_img, mask, (float*)d_out);
}